// round 1
// baseline (speedup 1.0000x reference)
#include <cuda_runtime.h>
#include <cuda_bf16.h>
#include <cstdint>

#define BB 32
#define CC 80
#define HH 128
#define WW 128
#define HWSZ (HH * WW)      // 16384
#define KK 100
#define CAP 32768           // candidate slots per batch
#define NBINS 1024

// Scratch (static device memory: allocation-free per harness rules)
__device__ unsigned int g_cnt[BB];
__device__ uint2 g_cand[BB * CAP];   // 8 MB

// ---------------------------------------------------------------------------
__global__ void k_zero() {
    if (threadIdx.x < BB) g_cnt[threadIdx.x] = 0u;
}

// ---------------------------------------------------------------------------
// Load one row (float4 per lane), compute horizontal 3-max per component.
// Warp lanes = 32 consecutive float4 column-groups of the same row.
__device__ __forceinline__ void ldrow(const float4* __restrict__ fp4, int y, int cg,
                                      float4& f4, float4& hm) {
    const float NEG = -1e30f;
    f4 = fp4[y * 32 + cg];
    float left  = __shfl_up_sync(0xffffffffu, f4.w, 1);
    float right = __shfl_down_sync(0xffffffffu, f4.x, 1);
    if (cg == 0)  left  = NEG;
    if (cg == 31) right = NEG;
    hm.x = fmaxf(fmaxf(left, f4.x), f4.y);
    hm.y = fmaxf(fmaxf(f4.x, f4.y), f4.z);
    hm.z = fmaxf(fmaxf(f4.y, f4.z), f4.w);
    hm.w = fmaxf(fmaxf(f4.z, f4.w), right);
}

__device__ __forceinline__ int val_bin(float v) {
    int bin = (int)(v * (float)NBINS);
    return max(0, min(NBINS - 1, bin));
}

// One block per (b, c) plane. 512 threads: 32 col-groups x 16 row-segments(8 rows).
__global__ __launch_bounds__(512) void k_stage1(const float* __restrict__ fmap) {
    __shared__ int hist[NBINS];
    __shared__ int s_tbin;
    __shared__ unsigned s_lcount, s_lc2, s_base;

    const int plane = blockIdx.x;
    const int b = plane / CC;
    const int c = plane % CC;
    const float* __restrict__ fp = fmap + (size_t)plane * HWSZ;
    const float4* __restrict__ fp4 = (const float4*)fp;

    const int t = threadIdx.x;
    for (int i = t; i < NBINS; i += 512) hist[i] = 0;
    if (t == 0) { s_lcount = 0u; s_lc2 = 0u; s_tbin = NBINS; }
    __syncthreads();

    const int cg = t & 31;            // column group (4 consecutive x)
    const int y0 = (t >> 5) * 8;      // first row of this thread's segment
    const float NEG = -1e30f;

    float4 fcur, fnext;
    float4 hprev, hcur, hnext;

    if (y0 == 0) {
        hprev = make_float4(NEG, NEG, NEG, NEG);
    } else {
        float4 fd;
        ldrow(fp4, y0 - 1, cg, fd, hprev);
    }
    ldrow(fp4, y0, cg, fcur, hcur);

    unsigned mask = 0u;   // survivor mask: bit = r*4 + component
#pragma unroll
    for (int r = 0; r < 8; r++) {
        const int y = y0 + r;
        if (y == HH - 1) {
            hnext = make_float4(NEG, NEG, NEG, NEG);
            fnext = fcur;
        } else {
            ldrow(fp4, y + 1, cg, fnext, hnext);
        }
        float4 vm;
        vm.x = fmaxf(fmaxf(hprev.x, hcur.x), hnext.x);
        vm.y = fmaxf(fmaxf(hprev.y, hcur.y), hnext.y);
        vm.z = fmaxf(fmaxf(hprev.z, hcur.z), hnext.z);
        vm.w = fmaxf(fmaxf(hprev.w, hcur.w), hnext.w);

        const float va[4] = {fcur.x, fcur.y, fcur.z, fcur.w};
        const float vb[4] = {vm.x, vm.y, vm.z, vm.w};
#pragma unroll
        for (int q = 0; q < 4; q++) {
            if (va[q] >= vb[q]) {            // local maximum of its 3x3 window
                atomicAdd(&hist[val_bin(va[q])], 1);
                mask |= 1u << (r * 4 + q);
            }
        }
        hprev = hcur; hcur = hnext; fcur = fnext;
    }
    __syncthreads();

    // Inclusive suffix-sum of hist (Hillis-Steele), 512 threads over 1024 bins.
    for (int off = 1; off < NBINS; off <<= 1) {
        int v0 = (t + off < NBINS) ? hist[t + off] : 0;
        int v1 = (t + 512 + off < NBINS) ? hist[t + 512 + off] : 0;
        __syncthreads();
        hist[t] += v0;
        hist[t + 512] += v1;
        __syncthreads();
    }

    const int total = hist[0];
    const int need = min(KK, total);
    if (need > 0) {
        // crossing bin: suffix(i) >= need, suffix(i+1) < need  (unique)
        for (int i = t; i < NBINS; i += 512) {
            int nx = (i == NBINS - 1) ? 0 : hist[i + 1];
            if (hist[i] >= need && nx < need) s_tbin = i;
        }
    }
    __syncthreads();
    const int tbin = s_tbin;

    // Count passing candidates, then block-aggregated append to g_cand[b].
    unsigned pmask = 0u;
    int mycnt = 0;
    {
        unsigned m = mask;
        while (m) {
            int bit = __ffs(m) - 1; m &= m - 1;
            int r = bit >> 2, q = bit & 3;
            int pos = (y0 + r) * WW + cg * 4 + q;
            float v = fp[pos];
            if (val_bin(v) >= tbin) { pmask |= 1u << bit; mycnt++; }
        }
    }
    if (mycnt) atomicAdd(&s_lcount, (unsigned)mycnt);
    __syncthreads();
    if (t == 0) s_base = atomicAdd(&g_cnt[b], s_lcount);
    __syncthreads();
    const unsigned base = s_base;
    if (mycnt) {
        unsigned slot = atomicAdd(&s_lc2, (unsigned)mycnt);
        unsigned m = pmask;
        while (m) {
            int bit = __ffs(m) - 1; m &= m - 1;
            int r = bit >> 2, q = bit & 3;
            int pos = (y0 + r) * WW + cg * 4 + q;
            float v = fp[pos];
            unsigned g = base + slot++;
            if (g < CAP)
                g_cand[(size_t)b * CAP + g] =
                    make_uint2(__float_as_uint(v), (unsigned)(c * HWSZ + pos));
        }
    }
}

// ---------------------------------------------------------------------------
// One block per batch: radix-select the 100th value, collect >= T, bitonic-sort,
// gather wh/reg, write bboxes | scores | clses.
__global__ __launch_bounds__(512) void k_stage2(const float* __restrict__ wh,
                                                const float* __restrict__ reg,
                                                float* __restrict__ out) {
    __shared__ int whist[16][256];          // warp-private histograms
    __shared__ int hist[256];
    __shared__ unsigned long long keys[2048];
    __shared__ int s_byte, s_above, s_wcnt;

    const int b = blockIdx.x;
    const int t = threadIdx.x;
    const int w = t >> 5;
    const int M = min((int)g_cnt[b], CAP);
    const uint2* __restrict__ cand = g_cand + (size_t)b * CAP;

    unsigned T = 0u;
    if (M > KK) {
        unsigned prefix = 0u, prefmask = 0u;
        int k = KK;
        for (int p = 3; p >= 0; p--) {
            for (int i = t; i < 16 * 256; i += 512) ((int*)whist)[i] = 0;
            __syncthreads();
            const int sh = p * 8;
            for (int i = t; i < M; i += 512) {
                unsigned v = cand[i].x;
                if ((v & prefmask) == prefix)
                    atomicAdd(&whist[w][(v >> sh) & 255], 1);
            }
            __syncthreads();
            if (t < 256) {
                int s = 0;
#pragma unroll
                for (int j = 0; j < 16; j++) s += whist[j][t];
                hist[t] = s;
            }
            __syncthreads();
            // inclusive suffix scan over 256 bins
            for (int off = 1; off < 256; off <<= 1) {
                int v = 0;
                if (t < 256 && t + off < 256) v = hist[t + off];
                __syncthreads();
                if (t < 256) hist[t] += v;
                __syncthreads();
            }
            if (t < 256) {
                int nx = (t == 255) ? 0 : hist[t + 1];
                if (hist[t] >= k && nx < k) { s_byte = t; s_above = nx; }
            }
            __syncthreads();
            prefix |= ((unsigned)s_byte) << sh;
            prefmask |= 0xFFu << sh;
            k -= s_above;
            __syncthreads();
        }
        T = prefix;   // exact value bits of the 100th-largest candidate
    }

    if (t == 0) s_wcnt = 0;
    for (int i = t; i < 2048; i += 512) keys[i] = 0ull;
    __syncthreads();
    for (int i = t; i < M; i += 512) {
        uint2 cv = cand[i];
        if (cv.x >= T) {
            int s = atomicAdd(&s_wcnt, 1);
            if (s < 2048)
                keys[s] = ((unsigned long long)cv.x << 32) |
                          (unsigned long long)(0xFFFFFFFFu - cv.y);
        }
    }
    __syncthreads();

    // bitonic sort ascending; top-100 end up at indices 2047..1948
    for (int kk2 = 2; kk2 <= 2048; kk2 <<= 1) {
        for (int j = kk2 >> 1; j > 0; j >>= 1) {
            for (int i = t; i < 2048; i += 512) {
                int ixj = i ^ j;
                if (ixj > i) {
                    unsigned long long a = keys[i], cc2 = keys[ixj];
                    bool up = ((i & kk2) == 0);
                    if ((a > cc2) == up) { keys[i] = cc2; keys[ixj] = a; }
                }
            }
            __syncthreads();
        }
    }

    const float* __restrict__ whb = wh + (size_t)b * 2 * HWSZ;
    const float* __restrict__ regb = reg + (size_t)b * 2 * HWSZ;
    for (int r = t; r < KK; r += 512) {
        unsigned long long key = keys[2047 - r];
        float val = __uint_as_float((unsigned)(key >> 32));
        unsigned pidx = 0xFFFFFFFFu - (unsigned)(key & 0xFFFFFFFFull);
        int cls = (int)(pidx >> 14);
        int pos = (int)(pidx & (HWSZ - 1));
        float yy = (float)(pos >> 7);
        float xx = (float)(pos & (WW - 1));
        float rx = regb[pos];
        float ry = regb[HWSZ + pos];
        float bw = whb[pos];
        float bh = whb[HWSZ + pos];
        float fx = xx + rx, fy = yy + ry;
        float hw2 = bw * 0.5f, hh2 = bh * 0.5f;
        float* bo = out + (size_t)(b * KK + r) * 4;
        bo[0] = fx - hw2;
        bo[1] = fy - hh2;
        bo[2] = fx + hw2;
        bo[3] = fy + hh2;
        out[BB * KK * 4 + b * KK + r] = val;                 // scores
        out[BB * KK * 4 + BB * KK + b * KK + r] = (float)cls; // classes
    }
}

// ---------------------------------------------------------------------------
extern "C" void kernel_launch(void* const* d_in, const int* in_sizes, int n_in,
                              void* d_out, int out_size) {
    const float* fmap = (const float*)d_in[0];
    const float* wh   = (const float*)d_in[1];
    const float* reg  = (const float*)d_in[2];
    float* out = (float*)d_out;

    k_zero<<<1, 32>>>();
    k_stage1<<<BB * CC, 512>>>(fmap);
    k_stage2<<<BB, 512>>>(wh, reg, out);
}